// round 8
// baseline (speedup 1.0000x reference)
#include <cuda_runtime.h>
#include <cuda_bf16.h>
#include <math.h>
#include <stdint.h>

#define SDIM 64
#define HDIM 128
#define KC   512
#define ADIM 8
#define TM   64
#define NT   256
#define NROWS_MAX 131072

// ---- smem arena (u32 offsets) ----
#define S_EN   0
#define S_B1   512
#define S_BH   640
#define S_NX2  768
#define S_T    832
#define S_MINU 896
#define S_CNT  960
#define S_CAND 1024      // u16[64][16] = 512 u32
#define S_FIN  1536
#define AB     1600
// era1 (layer1):  IN_S[3][64][36] @AB | W1S[3][128][36] @AB+6912   (end AB+20736)
// era2 (layer2):  HS[3][64][68]   @AB | WHC[3][128][20] @AB+13056  (end AB+20736)
// era3 (screen):  XBF[64][68] @AB | EB[64][68] @AB+4352 | DIST[64][260] @AB+8704
#define IN_S   AB
#define W1S    (AB + 6912)
#define HS     AB
#define WHC    (AB + 13056)
#define XBF    AB
#define EB     (AB + 4352)
#define EB_STR 68
#define DIST   (AB + 8704)
#define D_STR  260
#define ARENA_U32 (AB + 25344)   // 26944 u32 = 107,776 B -> 2 CTAs/SM

__device__ float g_probs[KC * ADIM];
__device__ float g_value[KC];
__device__ float g_enorm[KC];
__device__ uint32_t g_ebf[KC * HDIM / 2];       // bf16x2 codebook [code][k/2]
__device__ int g_emax = 0;
__device__ uint32_t g_w1s[3 * 128 * 32];        // W1^T 3-limb bf16x2 [s][j][kp]
__device__ uint32_t g_whs[3 * 128 * 64];        // Wh^T 3-limb bf16x2 [s][j][kp]
__device__ float g_x[(size_t)NROWS_MAX * HDIM]; // fp32 x scratch

// ---------------- helpers ----------------
__device__ __forceinline__ void mma_bf16(float c[4], const uint32_t a[4], const uint32_t b[2]) {
    asm volatile(
        "mma.sync.aligned.m16n8k16.row.col.f32.bf16.bf16.f32 "
        "{%0,%1,%2,%3}, {%4,%5,%6,%7}, {%8,%9}, {%0,%1,%2,%3};"
        : "+f"(c[0]), "+f"(c[1]), "+f"(c[2]), "+f"(c[3])
        : "r"(a[0]), "r"(a[1]), "r"(a[2]), "r"(a[3]), "r"(b[0]), "r"(b[1]));
}
__device__ __forceinline__ uint32_t fmap(float d) {
    uint32_t u = __float_as_uint(d);
    return (u >> 31) ? ~u : (u | 0x80000000u);
}
__device__ __forceinline__ float funmap(uint32_t m) {
    uint32_t u = (m & 0x80000000u) ? (m & 0x7FFFFFFFu) : ~m;
    return __uint_as_float(u);
}
__device__ __forceinline__ unsigned long long pk64(float d, int code) {
    return ((unsigned long long)fmap(d) << 32) | (uint32_t)code;
}
// split pair (a,b) into 3 bf16x2 limbs; a is low half (smaller k)
__device__ __forceinline__ void split3_pack(float a, float b,
                                            uint32_t& o1, uint32_t& o2, uint32_t& o3) {
    __nv_bfloat162 p1 = __floats2bfloat162_rn(a, b);
    float2 f1 = __bfloat1622float2(p1);
    float ra = a - f1.x, rb = b - f1.y;
    __nv_bfloat162 p2 = __floats2bfloat162_rn(ra, rb);
    float2 f2 = __bfloat1622float2(p2);
    __nv_bfloat162 p3 = __floats2bfloat162_rn(ra - f2.x, rb - f2.y);
    o1 = *reinterpret_cast<uint32_t*>(&p1);
    o2 = *reinterpret_cast<uint32_t*>(&p2);
    o3 = *reinterpret_cast<uint32_t*>(&p3);
}
// 6-pass limb product: c += (A1+A2+A3)(B1+B2+B3) to ~2^-26 relative
__device__ __forceinline__ void mma6(float c[4], uint32_t A[3][4], uint32_t B[3][2]) {
    mma_bf16(c, A[0], B[0]);
    mma_bf16(c, A[0], B[1]);
    mma_bf16(c, A[1], B[0]);
    mma_bf16(c, A[0], B[2]);
    mma_bf16(c, A[2], B[0]);
    mma_bf16(c, A[1], B[1]);
}

// ---------------------------------------------------------------------------
// Kernel W: split/transpose/pack both weight matrices (once per launch).
// ---------------------------------------------------------------------------
__global__ void w_kernel(const float* __restrict__ W1, const float* __restrict__ Wh) {
    int j = threadIdx.x;   // 128 cols
    for (int kp = 0; kp < SDIM / 2; kp++) {
        uint32_t o1, o2, o3;
        split3_pack(W1[(2 * kp) * HDIM + j], W1[(2 * kp + 1) * HDIM + j], o1, o2, o3);
        g_w1s[0 * 4096 + j * 32 + kp] = o1;
        g_w1s[1 * 4096 + j * 32 + kp] = o2;
        g_w1s[2 * 4096 + j * 32 + kp] = o3;
    }
    for (int kp = 0; kp < HDIM / 2; kp++) {
        uint32_t o1, o2, o3;
        split3_pack(Wh[(2 * kp) * HDIM + j], Wh[(2 * kp + 1) * HDIM + j], o1, o2, o3);
        g_whs[0 * 8192 + j * 64 + kp] = o1;
        g_whs[1 * 8192 + j * 64 + kp] = o2;
        g_whs[2 * 8192 + j * 64 + kp] = o3;
    }
}

// ---------------------------------------------------------------------------
// Kernel 0: per-code heads + bf16 codebook + norms + global max norm.
// ---------------------------------------------------------------------------
__global__ void head_kernel(const float* __restrict__ E,
                            const float* __restrict__ Wa,
                            const float* __restrict__ ba,
                            const float* __restrict__ Wv,
                            const float* __restrict__ bv) {
    int c = blockIdx.x * blockDim.x + threadIdx.x;
    if (c >= KC) return;
    float logit[ADIM];
#pragma unroll
    for (int a = 0; a < ADIM; a++) logit[a] = ba[a];
    float en = 0.f, val = bv[0], prev = 0.f;
    for (int k = 0; k < HDIM; k++) {
        float ev = E[c * HDIM + k];
        en  = fmaf(ev, ev, en);
        val = fmaf(ev, Wv[k], val);
        if (k & 1) {
            __nv_bfloat162 p = __floats2bfloat162_rn(prev, ev);
            g_ebf[c * 64 + (k >> 1)] = *reinterpret_cast<uint32_t*>(&p);
        } else prev = ev;
#pragma unroll
        for (int a = 0; a < ADIM; a++)
            logit[a] = fmaf(ev, Wa[k * ADIM + a], logit[a]);
    }
    float m = logit[0];
#pragma unroll
    for (int a = 1; a < ADIM; a++) m = fmaxf(m, logit[a]);
    float s = 0.f;
#pragma unroll
    for (int a = 0; a < ADIM; a++) { logit[a] = expf(logit[a] - m); s += logit[a]; }
    float inv = 1.f / s;
#pragma unroll
    for (int a = 0; a < ADIM; a++) g_probs[c * ADIM + a] = logit[a] * inv;
    g_value[c] = val;
    g_enorm[c] = en;
    atomicMax(&g_emax, __float_as_int(en));
}

// ---------------------------------------------------------------------------
// Fused kernel: 3-limb bf16 tensor MLP -> bf16 screen -> SIMD scan -> exact
// fp32 rescore. 64 rows/CTA, 256 threads, 2 CTAs/SM.
// ---------------------------------------------------------------------------
__global__ __launch_bounds__(NT, 2)
void fused_kernel(const float* __restrict__ in,
                  const float* __restrict__ b1,
                  const float* __restrict__ bh,
                  const float* __restrict__ E,
                  float* __restrict__ out,
                  int nrows) {
    extern __shared__ float smf[];
    uint32_t* smu = reinterpret_cast<uint32_t*>(smf);
    unsigned short* s_cand = reinterpret_cast<unsigned short*>(smu + S_CAND);

    const int tid  = threadIdx.x;
    const int wid  = tid >> 5, lane = tid & 31;
    const int l4 = lane >> 2, lm4 = lane & 3;
    const int row0 = blockIdx.x * TM;

    // ---- common init ----
    if (tid < 128) { smf[S_B1 + tid] = b1[tid]; smf[S_BH + tid] = bh[tid]; }
    if (tid < TM) { smu[S_MINU + tid] = 0xFFFFFFFFu; smu[S_CNT + tid] = 0; smf[S_NX2 + tid] = 0.f; }
    for (int i = tid; i < KC; i += NT) smf[S_EN + i] = g_enorm[i];

    // ---- load + split input tile [64][64] -> IN_S limbs ----
    for (int i = tid; i < TM * (SDIM / 2); i += NT) {
        int r = i >> 5, kp = i & 31;
        float2 v = *(const float2*)&in[(size_t)(row0 + r) * SDIM + 2 * kp];
        uint32_t o1, o2, o3;
        split3_pack(v.x, v.y, o1, o2, o3);
        smu[IN_S + 0 * 2304 + r * 36 + kp] = o1;
        smu[IN_S + 1 * 2304 + r * 36 + kp] = o2;
        smu[IN_S + 2 * 2304 + r * 36 + kp] = o3;
    }
    // ---- load W1 limbs into smem (re-strided 32->36) ----
    {
        const uint4* src = reinterpret_cast<const uint4*>(g_w1s);
        for (int q = tid; q < 3072; q += NT) {
            int s = q >> 10, j = (q >> 3) & 127, k4 = q & 7;
            *(uint4*)&smu[W1S + s * 4608 + j * 36 + 4 * k4] = src[q];
        }
    }
    __syncthreads();

    // MLP warp grid: wm = wid&3 (16-row m-tile), wn = wid>>2 (64-col half)
    const int wm = wid & 3, wn = wid >> 2;
    float c1[8][4];

    // ---- layer 1: h = relu(in @ W1 + b1), 6-limb-pass bf16 mma ----
#pragma unroll
    for (int nt = 0; nt < 8; nt++) {
        int col0 = 64 * wn + 8 * nt + 2 * lm4;
        c1[nt][0] = smf[S_B1 + col0];     c1[nt][1] = smf[S_B1 + col0 + 1];
        c1[nt][2] = c1[nt][0];            c1[nt][3] = c1[nt][1];
    }
#pragma unroll
    for (int ks = 0; ks < 4; ks++) {
        uint32_t A[3][4];
#pragma unroll
        for (int s = 0; s < 3; s++) {
            int base = IN_S + s * 2304 + (16 * wm + l4) * 36 + 8 * ks + lm4;
            A[s][0] = smu[base];           A[s][1] = smu[base + 8 * 36];
            A[s][2] = smu[base + 4];       A[s][3] = smu[base + 8 * 36 + 4];
        }
#pragma unroll
        for (int nt = 0; nt < 8; nt++) {
            int col = 64 * wn + 8 * nt + l4;
            uint32_t B[3][2];
#pragma unroll
            for (int s = 0; s < 3; s++) {
                int boff = W1S + s * 4608 + col * 36 + 8 * ks + lm4;
                B[s][0] = smu[boff]; B[s][1] = smu[boff + 4];
            }
            mma6(c1[nt], A, B);
        }
    }
    __syncthreads();   // layer-1 smem reads done; IN_S/W1S regions die

    // ---- h epilogue: relu + 3-limb split into HS ----
#pragma unroll
    for (int nt = 0; nt < 8; nt++) {
        int r0 = 16 * wm + l4, cp = 32 * wn + 4 * nt + lm4;
        uint32_t o1, o2, o3;
        split3_pack(fmaxf(c1[nt][0], 0.f), fmaxf(c1[nt][1], 0.f), o1, o2, o3);
        smu[HS + 0 * 4352 + r0 * 68 + cp] = o1;
        smu[HS + 1 * 4352 + r0 * 68 + cp] = o2;
        smu[HS + 2 * 4352 + r0 * 68 + cp] = o3;
        split3_pack(fmaxf(c1[nt][2], 0.f), fmaxf(c1[nt][3], 0.f), o1, o2, o3);
        smu[HS + 0 * 4352 + (r0 + 8) * 68 + cp] = o1;
        smu[HS + 1 * 4352 + (r0 + 8) * 68 + cp] = o2;
        smu[HS + 2 * 4352 + (r0 + 8) * 68 + cp] = o3;
    }
    __syncthreads();

    // ---- layer 2: x = relu(h @ Wh + bh); Wh limbs streamed in 4 k-chunks ----
    float c2[8][4];
#pragma unroll
    for (int nt = 0; nt < 8; nt++) {
        int col0 = 64 * wn + 8 * nt + 2 * lm4;
        c2[nt][0] = smf[S_BH + col0];     c2[nt][1] = smf[S_BH + col0 + 1];
        c2[nt][2] = c2[nt][0];            c2[nt][3] = c2[nt][1];
    }
#pragma unroll 1
    for (int cc = 0; cc < 4; cc++) {
        {
            const uint4* src = reinterpret_cast<const uint4*>(g_whs);
            for (int q = tid; q < 1536; q += NT) {
                int s = q >> 9, j = (q >> 2) & 127, k4 = q & 3;
                *(uint4*)&smu[WHC + s * 2560 + j * 20 + 4 * k4] =
                    src[(s * 128 + j) * 16 + 4 * cc + k4];
            }
        }
        __syncthreads();
#pragma unroll
        for (int ksl = 0; ksl < 2; ksl++) {
            int ks = 2 * cc + ksl;
            uint32_t A[3][4];
#pragma unroll
            for (int s = 0; s < 3; s++) {
                int base = HS + s * 4352 + (16 * wm + l4) * 68 + 8 * ks + lm4;
                A[s][0] = smu[base];           A[s][1] = smu[base + 8 * 68];
                A[s][2] = smu[base + 4];       A[s][3] = smu[base + 8 * 68 + 4];
            }
#pragma unroll
            for (int nt = 0; nt < 8; nt++) {
                int col = 64 * wn + 8 * nt + l4;
                uint32_t B[3][2];
#pragma unroll
                for (int s = 0; s < 3; s++) {
                    int boff = WHC + s * 2560 + col * 20 + 8 * ksl + lm4;
                    B[s][0] = smu[boff]; B[s][1] = smu[boff + 4];
                }
                mma6(c2[nt], A, B);
            }
        }
        __syncthreads();   // chunk reads done before next overwrite
    }

    // ---- x epilogue: relu -> XBF bf16 tile + g_x fp32 + row norms ----
    {
        float nx0 = 0.f, nx1 = 0.f;
        int r0 = 16 * wm + l4;
#pragma unroll
        for (int nt = 0; nt < 8; nt++) {
            int col0 = 64 * wn + 8 * nt + 2 * lm4, cp = col0 >> 1;
            float v00 = fmaxf(c2[nt][0], 0.f), v01 = fmaxf(c2[nt][1], 0.f);
            float v10 = fmaxf(c2[nt][2], 0.f), v11 = fmaxf(c2[nt][3], 0.f);
            __nv_bfloat162 p0 = __floats2bfloat162_rn(v00, v01);
            __nv_bfloat162 p1 = __floats2bfloat162_rn(v10, v11);
            smu[XBF + r0 * EB_STR + cp]       = *reinterpret_cast<uint32_t*>(&p0);
            smu[XBF + (r0 + 8) * EB_STR + cp] = *reinterpret_cast<uint32_t*>(&p1);
            *(float2*)&g_x[(size_t)(row0 + r0) * HDIM + col0]     = make_float2(v00, v01);
            *(float2*)&g_x[(size_t)(row0 + r0 + 8) * HDIM + col0] = make_float2(v10, v11);
            nx0 = fmaf(v00, v00, fmaf(v01, v01, nx0));
            nx1 = fmaf(v10, v10, fmaf(v11, v11, nx1));
        }
#pragma unroll
        for (int off = 1; off < 4; off <<= 1) {
            nx0 += __shfl_xor_sync(0xffffffffu, nx0, off);
            nx1 += __shfl_xor_sync(0xffffffffu, nx1, off);
        }
        if (lm4 == 0) {
            atomicAdd(&smf[S_NX2 + r0], nx0);
            atomicAdd(&smf[S_NX2 + r0 + 8], nx1);
        }
    }

    // ---- screen: 8 chunks of 64 codes, bf16 mma, distances stored in DIST ----
    const int wm2 = wid & 1, wn2 = wid >> 1;
    const uint32_t* xb = smu + XBF;
    uint32_t* eb = smu + EB;
    const uint4* esrc = reinterpret_cast<const uint4*>(g_ebf);

    uint32_t mk[2][2] = {{0xFFFFFFFFu, 0xFFFFFFFFu}, {0xFFFFFFFFu, 0xFFFFFFFFu}};

    uint4 pf[4];
#pragma unroll
    for (int s = 0; s < 4; s++) {
        int i = tid + s * NT;
        pf[s] = esrc[(i >> 4) * 16 + (i & 15)];
    }
    __syncthreads();   // XBF visible; EB region (dead era2) safe to write

#pragma unroll 1
    for (int ch = 0; ch < 8; ch++) {
#pragma unroll
        for (int s = 0; s < 4; s++) {
            int i = tid + s * NT;
            *(uint4*)&eb[(i >> 4) * EB_STR + (i & 15) * 4] = pf[s];
        }
        __syncthreads();
        if (ch < 7) {
#pragma unroll
            for (int s = 0; s < 4; s++) {
                int i = tid + s * NT;
                pf[s] = esrc[((ch + 1) * 64 + (i >> 4)) * 16 + (i & 15)];
            }
        }

        float dacc[2][2][4];
#pragma unroll
        for (int mt = 0; mt < 2; mt++)
#pragma unroll
            for (int nt = 0; nt < 2; nt++)
#pragma unroll
                for (int q = 0; q < 4; q++) dacc[mt][nt][q] = 0.f;

#pragma unroll
        for (int ks = 0; ks < 8; ks++) {
            const int ko = 8 * ks + lm4;
            uint32_t a[2][4], b[2][2];
#pragma unroll
            for (int mt = 0; mt < 2; mt++) {
                int r = wm2 * 32 + mt * 16 + l4;
                a[mt][0] = xb[r * EB_STR + ko];
                a[mt][1] = xb[(r + 8) * EB_STR + ko];
                a[mt][2] = xb[r * EB_STR + ko + 4];
                a[mt][3] = xb[(r + 8) * EB_STR + ko + 4];
            }
#pragma unroll
            for (int nt = 0; nt < 2; nt++) {
                int cc = wn2 * 16 + nt * 8 + l4;
                b[nt][0] = eb[cc * EB_STR + ko];
                b[nt][1] = eb[cc * EB_STR + ko + 4];
            }
#pragma unroll
            for (int mt = 0; mt < 2; mt++)
#pragma unroll
                for (int nt = 0; nt < 2; nt++)
                    mma_bf16(dacc[mt][nt], a[mt], b[nt]);
        }

#pragma unroll
        for (int nt = 0; nt < 2; nt++) {
            int code0 = ch * 64 + wn2 * 16 + nt * 8 + 2 * lm4;
            float en0 = smf[S_EN + code0], en1 = smf[S_EN + code0 + 1];
#pragma unroll
            for (int mt = 0; mt < 2; mt++) {
                int r = wm2 * 32 + mt * 16 + l4;
                float d00 = fmaf(-2.f, dacc[mt][nt][0], en0);
                float d01 = fmaf(-2.f, dacc[mt][nt][1], en1);
                float d10 = fmaf(-2.f, dacc[mt][nt][2], en0);
                float d11 = fmaf(-2.f, dacc[mt][nt][3], en1);
                __nv_bfloat162 p0 = __floats2bfloat162_rn(d00, d01);
                __nv_bfloat162 p1 = __floats2bfloat162_rn(d10, d11);
                smu[DIST + r * D_STR + (code0 >> 1)]       = *reinterpret_cast<uint32_t*>(&p0);
                smu[DIST + (r + 8) * D_STR + (code0 >> 1)] = *reinterpret_cast<uint32_t*>(&p1);
                float2 f0 = __bfloat1622float2(p0);
                float2 f1 = __bfloat1622float2(p1);
                mk[mt][0] = min(mk[mt][0], min(fmap(f0.x), fmap(f0.y)));
                mk[mt][1] = min(mk[mt][1], min(fmap(f1.x), fmap(f1.y)));
            }
        }
        __syncthreads();
    }

#pragma unroll
    for (int mt = 0; mt < 2; mt++) {
        int r = wm2 * 32 + mt * 16 + l4;
        atomicMin(&smu[S_MINU + r], mk[mt][0]);
        atomicMin(&smu[S_MINU + r + 8], mk[mt][1]);
    }
    __syncthreads();

    if (tid < TM) {
        float dmin = funmap(smu[S_MINU + tid]);
        float nx2 = smf[S_NX2 + tid];
        float em = sqrtf(__int_as_float(g_emax));
        smf[S_T + tid] = dmin + 0.045f * sqrtf(nx2) * em
                       + 0.00390625f * (nx2 + 1.f) + 1e-6f;
    }
    __syncthreads();

    // ---- SIMD scan of stored bf16 distances ----
    {
        int row = tid >> 2, q = tid & 3;
        float T = smf[S_T + row];
        __nv_bfloat16 Tb = __float2bfloat16_ru(T);
        __nv_bfloat162 T2 = __bfloat162bfloat162(Tb);
        float Tf = __bfloat162float(Tb);
        const uint32_t* dr = smu + DIST + row * D_STR + q * 64;
#pragma unroll 1
        for (int j = 0; j < 16; j++) {
            uint4 v = *(const uint4*)&dr[j * 4];
            uint32_t ws[4] = {v.x, v.y, v.z, v.w};
            uint32_t any = 0;
#pragma unroll
            for (int w = 0; w < 4; w++) {
                __nv_bfloat162 p = *reinterpret_cast<__nv_bfloat162*>(&ws[w]);
                __nv_bfloat162 m = __hle2(p, T2);
                any |= *reinterpret_cast<uint32_t*>(&m);
            }
            if (any) {
#pragma unroll
                for (int w = 0; w < 4; w++) {
                    __nv_bfloat162 p = *reinterpret_cast<__nv_bfloat162*>(&ws[w]);
                    float2 f = __bfloat1622float2(p);
                    int code = (q * 64 + j * 4 + w) * 2;
                    if (f.x <= Tf) {
                        int pos = atomicAdd((int*)&smu[S_CNT + row], 1);
                        if (pos < 16) s_cand[row * 16 + pos] = (unsigned short)code;
                    }
                    if (f.y <= Tf) {
                        int pos = atomicAdd((int*)&smu[S_CNT + row], 1);
                        if (pos < 16) s_cand[row * 16 + pos] = (unsigned short)(code + 1);
                    }
                }
            }
        }
    }
    __syncthreads();

    // ---- exact fp32 rescore by owning warp (x from g_x, E from L2) ----
    const int rbase = wid * 8;
#pragma unroll 1
    for (int i = 0; i < 8; i++) {
        int row = rbase + i;
        int cnt = (int)smu[S_CNT + row];
        float4 xv = *(const float4*)&g_x[(size_t)(row0 + row) * HDIM + 4 * lane];
        unsigned long long best = ~0ULL;
        if (cnt <= 16) {
#pragma unroll 1
            for (int j = 0; j < cnt; j++) {
                int code = s_cand[row * 16 + j];
                float4 ev = *(const float4*)&E[(size_t)code * HDIM + 4 * lane];
                float p = fmaf(xv.x, ev.x, fmaf(xv.y, ev.y,
                          fmaf(xv.z, ev.z, xv.w * ev.w)));
#pragma unroll
                for (int off = 16; off; off >>= 1)
                    p += __shfl_xor_sync(0xffffffffu, p, off);
                unsigned long long k = pk64(fmaf(-2.f, p, smf[S_EN + code]), code);
                if (k < best) best = k;
            }
        } else {
#pragma unroll 1
            for (int code = 0; code < KC; code++) {
                float4 ev = *(const float4*)&E[(size_t)code * HDIM + 4 * lane];
                float p = fmaf(xv.x, ev.x, fmaf(xv.y, ev.y,
                          fmaf(xv.z, ev.z, xv.w * ev.w)));
#pragma unroll
                for (int off = 16; off; off >>= 1)
                    p += __shfl_xor_sync(0xffffffffu, p, off);
                unsigned long long k = pk64(fmaf(-2.f, p, smf[S_EN + code]), code);
                if (k < best) best = k;
            }
        }
        if (lane == 0) smu[S_FIN + row] = (uint32_t)(best & 0xFFFFFFFFULL);
    }
    __syncthreads();

    // ---- gather outputs ----
    if (tid < TM) {
        int bidx = (int)smu[S_FIN + tid];
        size_t grow = (size_t)(row0 + tid);
        float4 p0 = *(const float4*)&g_probs[bidx * ADIM];
        float4 p1 = *(const float4*)&g_probs[bidx * ADIM + 4];
        *(float4*)&out[grow * ADIM]     = p0;
        *(float4*)&out[grow * ADIM + 4] = p1;
        out[(size_t)nrows * ADIM + grow] = g_value[bidx];
    }
}

// ---------------------------------------------------------------------------
extern "C" void kernel_launch(void* const* d_in, const int* in_sizes, int n_in,
                              void* d_out, int out_size) {
    const float* in = (const float*)d_in[0];
    const float* W1 = (const float*)d_in[1];
    const float* b1 = (const float*)d_in[2];
    const float* Wh = (const float*)d_in[3];
    const float* bh = (const float*)d_in[4];
    const float* E  = (const float*)d_in[5];
    const float* Wa = (const float*)d_in[6];
    const float* ba = (const float*)d_in[7];
    const float* Wv = (const float*)d_in[8];
    const float* bv = (const float*)d_in[9];
    float* out = (float*)d_out;

    const int nrows = in_sizes[0] / SDIM;  // 131072

    w_kernel<<<1, 128>>>(W1, Wh);
    head_kernel<<<(KC + 255) / 256, 256>>>(E, Wa, ba, Wv, bv);

    const int smem_bytes = ARENA_U32 * (int)sizeof(uint32_t);  // 107,776 B
    cudaFuncSetAttribute(fused_kernel,
                         cudaFuncAttributeMaxDynamicSharedMemorySize, smem_bytes);
    fused_kernel<<<nrows / TM, NT, smem_bytes>>>(in, b1, bh, E, out, nrows);
}